// round 5
// baseline (speedup 1.0000x reference)
#include <cuda_runtime.h>
#include <cstdint>
#include <math.h>

#define SEQ 4096
#define DIM 1024

// Scratch (allocation-free rule: device globals)
__device__ float g_x[SEQ * DIM];          // tf32-rounded x
__device__ float g_wq[DIM * DIM];
__device__ float g_wk[DIM * DIM];
__device__ float g_wv[DIM * DIM];
__device__ float g_q[SEQ * DIM];
__device__ float g_k[SEQ * DIM];
__device__ float g_v[SEQ * DIM];          // holds V^T [DIM, SEQ]
__device__ float g_s[(size_t)SEQ * SEQ];

// ---------------------------------------------------------------------------
// PTX helpers (base-target-safe: cp.async + mma.sync only)
// ---------------------------------------------------------------------------
__device__ __forceinline__ uint32_t smem_u32(const void* p) {
    uint32_t a;
    asm("{ .reg .u64 t; cvta.to.shared.u64 t, %1; cvt.u32.u64 %0, t; }" : "=r"(a) : "l"(p));
    return a;
}
__device__ __forceinline__ void cp16(uint32_t s, const void* g) {
    asm volatile("cp.async.cg.shared.global [%0], [%1], 16;" :: "r"(s), "l"(g));
}
__device__ __forceinline__ void cp_commit() {
    asm volatile("cp.async.commit_group;" ::: "memory");
}
__device__ __forceinline__ float round_tf32f(float x) {
    uint32_t y;
    asm("cvt.rna.tf32.f32 %0, %1;" : "=r"(y) : "f"(x));
    return __uint_as_float(y);
}
__device__ __forceinline__ void mma_tf32(float* c, const uint32_t* a, const uint32_t* b) {
    asm volatile(
        "mma.sync.aligned.m16n8k8.row.col.f32.tf32.tf32.f32 "
        "{%0,%1,%2,%3}, {%4,%5,%6,%7}, {%8,%9}, {%0,%1,%2,%3};"
        : "+f"(c[0]), "+f"(c[1]), "+f"(c[2]), "+f"(c[3])
        : "r"(a[0]), "r"(a[1]), "r"(a[2]), "r"(a[3]), "r"(b[0]), "r"(b[1]));
}

// ---------------------------------------------------------------------------
// Elementwise tf32 rounding pre-pass
// ---------------------------------------------------------------------------
__global__ __launch_bounds__(256)
void round_arr(const float* __restrict__ in, float* __restrict__ out, int n4)
{
    int i = blockIdx.x * blockDim.x + threadIdx.x;
    if (i < n4) {
        float4 v = ((const float4*)in)[i];
        v.x = round_tf32f(v.x); v.y = round_tf32f(v.y);
        v.z = round_tf32f(v.z); v.w = round_tf32f(v.w);
        ((float4*)out)[i] = v;
    }
}

// ---------------------------------------------------------------------------
// tf32 mma.sync NT GEMM: C[M,N] = scale * A[M,K] * B^T,  B stored [N,K] row-major.
// Operands must be pre-rounded to tf32.
// BM=128, BN=256, BK=16, 4-stage cp.async (1 sync/iter), 256 threads,
// 8 warps (2x4), 64x64 per warp (0.5 LDS per HMMA).
// Requires M%128==0, N%256==0, K%16==0.
// ---------------------------------------------------------------------------
#define SW 20                       // smem words per 16-float row (conflict-free)
#define A_TW (128 * SW)             // A tile words
#define B_TW (256 * SW)             // B tile words
#define STG_W (A_TW + B_TW)         // words per stage
#define NSTG 4
#define SMEM_BYTES (NSTG * STG_W * 4)   // 122880

template <bool ROUND_OUT>
__global__ __launch_bounds__(256, 1)
void gemm_mma(const float* __restrict__ A, const float* __restrict__ B,
              float* __restrict__ C, int M, int N, int K, float scale)
{
    extern __shared__ float sm[];
    const int tid  = threadIdx.x;
    const int lane = tid & 31;
    const int wid  = tid >> 5;
    const int gid  = lane >> 2;    // 0..7
    const int tig  = lane & 3;     // 0..3
    const int wm   = (wid & 1) * 64;      // 2 warp-rows
    const int wn   = (wid >> 1) * 64;     // 4 warp-cols
    const int row0 = blockIdx.y * 128;
    const int col0 = blockIdx.x * 256;

    const uint32_t sm0 = smem_u32(sm);

    float acc[4][8][4];
#pragma unroll
    for (int i = 0; i < 4; i++)
#pragma unroll
        for (int j = 0; j < 8; j++)
#pragma unroll
            for (int q = 0; q < 4; q++) acc[i][j][q] = 0.0f;

    const int KT = K >> 4;   // K / 16

    // cp.async: 1536 16B-chunks per stage (A:512, B:1024) = 6 per thread
    auto issue = [&](int slot, int kt) {
        const uint32_t sa = sm0 + (slot * STG_W) * 4;
        const uint32_t sb = sa + A_TW * 4;
        const int kbase = kt * 16;
#pragma unroll
        for (int t = 0; t < 2; t++) {
            int c = tid + t * 256;            // 0..511
            int r = c >> 2, ko = (c & 3) * 4;
            cp16(sa + (r * SW + ko) * 4, A + (size_t)(row0 + r) * K + kbase + ko);
        }
#pragma unroll
        for (int t = 0; t < 4; t++) {
            int c = tid + t * 256;            // 0..1023
            int r = c >> 2, ko = (c & 3) * 4;
            cp16(sb + (r * SW + ko) * 4, B + (size_t)(col0 + r) * K + kbase + ko);
        }
    };

    // prologue: 3 stages in flight
    issue(0, 0); cp_commit();
    issue(1, 1); cp_commit();
    issue(2, 2); cp_commit();

    for (int kt = 0; kt < KT; kt++) {
        asm volatile("cp.async.wait_group 2;" ::: "memory");
        __syncthreads();
        // slot (kt+3)&3 == (kt-1)&3: all warps finished kt-1 before the sync.
        if (kt + 3 < KT) issue((kt + 3) & 3, kt + 3);
        cp_commit();

        const float* Sa = sm + (kt & 3) * STG_W;
        const float* Sb = Sa + A_TW;
        const float* pa = Sa + (wm + gid) * SW;   // per-warp row base
        const float* pb = Sb + (wn + gid) * SW;

#pragma unroll
        for (int ks = 0; ks < 2; ks++) {
            const int kw = ks * 8 + tig;
            uint32_t af[4][4], bf[8][2];
#pragma unroll
            for (int mt = 0; mt < 4; mt++) {
                af[mt][0] = __float_as_uint(pa[(mt * 16) * SW + kw]);
                af[mt][1] = __float_as_uint(pa[(mt * 16 + 8) * SW + kw]);
                af[mt][2] = __float_as_uint(pa[(mt * 16) * SW + kw + 4]);
                af[mt][3] = __float_as_uint(pa[(mt * 16 + 8) * SW + kw + 4]);
            }
#pragma unroll
            for (int nt = 0; nt < 8; nt++) {
                bf[nt][0] = __float_as_uint(pb[(nt * 8) * SW + kw]);
                bf[nt][1] = __float_as_uint(pb[(nt * 8) * SW + kw + 4]);
            }
#pragma unroll
            for (int mt = 0; mt < 4; mt++)
#pragma unroll
                for (int nt = 0; nt < 8; nt++)
                    mma_tf32(acc[mt][nt], af[mt], bf[nt]);
        }
    }

    // Epilogue: c0/c1 at (row, 2*tig), c2/c3 at (row+8, 2*tig)
#pragma unroll
    for (int mt = 0; mt < 4; mt++) {
#pragma unroll
        for (int nt = 0; nt < 8; nt++) {
            const int r = row0 + wm + mt * 16 + gid;
            const int c = col0 + wn + nt * 8 + 2 * tig;
            float o0 = acc[mt][nt][0] * scale, o1 = acc[mt][nt][1] * scale;
            float o2 = acc[mt][nt][2] * scale, o3 = acc[mt][nt][3] * scale;
            if (ROUND_OUT) {
                o0 = round_tf32f(o0); o1 = round_tf32f(o1);
                o2 = round_tf32f(o2); o3 = round_tf32f(o3);
            }
            *(float2*)(C + (size_t)r * N + c)       = make_float2(o0, o1);
            *(float2*)(C + (size_t)(r + 8) * N + c) = make_float2(o2, o3);
        }
    }
}

// ---------------------------------------------------------------------------
// Row softmax over S[SEQ, N]; one block per row. Stores tf32-rounded P.
// ---------------------------------------------------------------------------
__global__ __launch_bounds__(256)
void softmax_rows(float* __restrict__ S, int N)
{
    __shared__ float buf[SEQ];
    __shared__ float red[32];
    const int tid   = threadIdx.x;
    const int lane  = tid & 31;
    const int warp  = tid >> 5;
    const int nwarp = blockDim.x >> 5;
    float* row = S + (size_t)blockIdx.x * N;

    float lmax = -1e30f;
    for (int i = tid; i < N; i += blockDim.x) {
        float v = row[i];
        buf[i] = v;
        lmax = fmaxf(lmax, v);
    }
#pragma unroll
    for (int o = 16; o > 0; o >>= 1)
        lmax = fmaxf(lmax, __shfl_xor_sync(0xffffffffu, lmax, o));
    if (lane == 0) red[warp] = lmax;
    __syncthreads();
    if (tid < 32) {
        float v = (tid < nwarp) ? red[tid] : -1e30f;
#pragma unroll
        for (int o = 16; o > 0; o >>= 1)
            v = fmaxf(v, __shfl_xor_sync(0xffffffffu, v, o));
        red[tid] = v;
    }
    __syncthreads();
    const float rmax = red[0];
    __syncthreads();

    float lsum = 0.0f;
    for (int i = tid; i < N; i += blockDim.x) {
        float e = __expf(buf[i] - rmax);
        buf[i] = e;
        lsum += e;
    }
#pragma unroll
    for (int o = 16; o > 0; o >>= 1)
        lsum += __shfl_xor_sync(0xffffffffu, lsum, o);
    if (lane == 0) red[warp] = lsum;
    __syncthreads();
    if (tid < 32) {
        float v = (tid < nwarp) ? red[tid] : 0.0f;
#pragma unroll
        for (int o = 16; o > 0; o >>= 1)
            v += __shfl_xor_sync(0xffffffffu, v, o);
        red[tid] = v;
    }
    __syncthreads();
    const float inv = 1.0f / red[0];

    for (int i = tid; i < N; i += blockDim.x)
        row[i] = round_tf32f(buf[i] * inv);
}

// ---------------------------------------------------------------------------
extern "C" void kernel_launch(void* const* d_in, const int* in_sizes, int n_in,
                              void* d_out, int out_size)
{
    const float* x  = (const float*)d_in[0];
    const float* Wq = (const float*)d_in[1];
    const float* Wk = (const float*)d_in[2];
    const float* Wv = (const float*)d_in[3];
    float* out = (float*)d_out;

    float *xp, *wqp, *wkp, *wvp, *qp, *kp, *vp, *sp;
    cudaGetSymbolAddress((void**)&xp,  g_x);
    cudaGetSymbolAddress((void**)&wqp, g_wq);
    cudaGetSymbolAddress((void**)&wkp, g_wk);
    cudaGetSymbolAddress((void**)&wvp, g_wv);
    cudaGetSymbolAddress((void**)&qp,  g_q);
    cudaGetSymbolAddress((void**)&kp,  g_k);
    cudaGetSymbolAddress((void**)&vp,  g_v);
    cudaGetSymbolAddress((void**)&sp,  g_s);

    cudaFuncSetAttribute(gemm_mma<true>,  cudaFuncAttributeMaxDynamicSharedMemorySize, SMEM_BYTES);
    cudaFuncSetAttribute(gemm_mma<false>, cudaFuncAttributeMaxDynamicSharedMemorySize, SMEM_BYTES);

    const float scale = 1.0f / 32.0f;  // 1/sqrt(1024)

    // tf32 pre-rounding of raw inputs
    round_arr<<<(SEQ * DIM / 4 + 255) / 256, 256>>>(x,  xp,  SEQ * DIM / 4);
    round_arr<<<(DIM * DIM / 4 + 255) / 256, 256>>>(Wq, wqp, DIM * DIM / 4);
    round_arr<<<(DIM * DIM / 4 + 255) / 256, 256>>>(Wk, wkp, DIM * DIM / 4);
    round_arr<<<(DIM * DIM / 4 + 255) / 256, 256>>>(Wv, wvp, DIM * DIM / 4);

    // Q = X @ Wq^T   [4096,1024]  (rounded for S gemm)
    gemm_mma<true><<<dim3(DIM / 256, SEQ / 128), 256, SMEM_BYTES>>>(xp, wqp, qp, SEQ, DIM, DIM, 1.0f);
    // K = X @ Wk^T   [4096,1024]  (rounded)
    gemm_mma<true><<<dim3(DIM / 256, SEQ / 128), 256, SMEM_BYTES>>>(xp, wkp, kp, SEQ, DIM, DIM, 1.0f);
    // V^T = Wv @ X^T [1024,4096]  (rounded for O gemm)
    gemm_mma<true><<<dim3(SEQ / 256, DIM / 128), 256, SMEM_BYTES>>>(wvp, xp, vp, DIM, SEQ, DIM, 1.0f);
    // S = (Q @ K^T) * scale  [4096,4096]  (softmax rounds)
    gemm_mma<false><<<dim3(SEQ / 256, SEQ / 128), 256, SMEM_BYTES>>>(qp, kp, sp, SEQ, SEQ, DIM, scale);
    // softmax rows (stores tf32-rounded P)
    softmax_rows<<<SEQ, 256>>>(sp, SEQ);
    // O = P @ (V^T)^T  [4096,1024]  (final, no rounding)
    gemm_mma<false><<<dim3(DIM / 256, SEQ / 128), 256, SMEM_BYTES>>>(sp, vp, out, SEQ, DIM, SEQ, 1.0f);
}

// round 6
// speedup vs baseline: 1.1031x; 1.1031x over previous
#include <cuda_runtime.h>
#include <cstdint>
#include <math.h>

#define SEQ 4096
#define DIM 1024

// Scratch (allocation-free rule: device globals)
__device__ float g_x[SEQ * DIM];            // tf32-rounded x
__device__ float g_wqk[2 * DIM * DIM];      // tf32-rounded [Wq; Wk] packed
__device__ float g_wv[DIM * DIM];
__device__ float g_qk[SEQ * 2 * DIM];       // [Q | K] packed, ldc = 2048
__device__ float g_v[SEQ * DIM];            // holds V^T [DIM, SEQ]
__device__ float g_s[(size_t)SEQ * SEQ];    // exp(S) (unnormalized P)
__device__ float g_rinv[SEQ];               // 1 / rowsum

// ---------------------------------------------------------------------------
// PTX helpers (base-target-safe: cp.async + mma.sync only)
// ---------------------------------------------------------------------------
__device__ __forceinline__ uint32_t smem_u32(const void* p) {
    uint32_t a;
    asm("{ .reg .u64 t; cvta.to.shared.u64 t, %1; cvt.u32.u64 %0, t; }" : "=r"(a) : "l"(p));
    return a;
}
__device__ __forceinline__ void cp16(uint32_t s, const void* g) {
    asm volatile("cp.async.cg.shared.global [%0], [%1], 16;" :: "r"(s), "l"(g));
}
__device__ __forceinline__ void cp_commit() {
    asm volatile("cp.async.commit_group;" ::: "memory");
}
__device__ __forceinline__ float round_tf32f(float x) {
    uint32_t y;
    asm("cvt.rna.tf32.f32 %0, %1;" : "=r"(y) : "f"(x));
    return __uint_as_float(y);
}
__device__ __forceinline__ void mma_tf32(float* c, const uint32_t* a, const uint32_t* b) {
    asm volatile(
        "mma.sync.aligned.m16n8k8.row.col.f32.tf32.tf32.f32 "
        "{%0,%1,%2,%3}, {%4,%5,%6,%7}, {%8,%9}, {%0,%1,%2,%3};"
        : "+f"(c[0]), "+f"(c[1]), "+f"(c[2]), "+f"(c[3])
        : "r"(a[0]), "r"(a[1]), "r"(a[2]), "r"(a[3]), "r"(b[0]), "r"(b[1]));
}

// ---------------------------------------------------------------------------
// Elementwise tf32 rounding pre-pass
// ---------------------------------------------------------------------------
__global__ __launch_bounds__(256)
void round_arr(const float* __restrict__ in, float* __restrict__ out, int n4)
{
    int i = blockIdx.x * blockDim.x + threadIdx.x;
    if (i < n4) {
        float4 v = ((const float4*)in)[i];
        v.x = round_tf32f(v.x); v.y = round_tf32f(v.y);
        v.z = round_tf32f(v.z); v.w = round_tf32f(v.w);
        ((float4*)out)[i] = v;
    }
}

// ---------------------------------------------------------------------------
// tf32 mma.sync NT GEMM: C[M,N] = epi(scale * A[M,K] * B^T)
// A row-major [M,K] stride lda; B row-major [N,K] stride ldb; C stride ldc.
// Operands must be pre-rounded to tf32.
// BM=BN=128, BK=16, 4-stage cp.async (1 sync/iter), 256 threads, 8 warps (2x4),
// 64x32 per warp. Requires M%128==0, N%128==0, K%16==0.
// EPI: 0=none, 1=tf32-round, 2=tf32-round(exp(scale*acc)).
// DIV: multiply output rows by rowinv[r] (softmax normalization).
// ---------------------------------------------------------------------------
#define SW 20                      // smem words per 16-float row (conflict-free)
#define TILE_W (128 * SW)          // words per A (or B) tile
#define NSTG 4
#define SMEM_BYTES (NSTG * 2 * TILE_W * 4)   // 81920

template <int EPI, bool DIV>
__global__ __launch_bounds__(256, 2)
void gemm_mma(const float* __restrict__ A, const float* __restrict__ B,
              float* __restrict__ C, int K, int lda, int ldb, int ldc,
              float scale, const float* __restrict__ rowinv)
{
    extern __shared__ float sm[];
    const int tid  = threadIdx.x;
    const int lane = tid & 31;
    const int wid  = tid >> 5;
    const int gid  = lane >> 2;    // 0..7
    const int tig  = lane & 3;     // 0..3
    const int wm   = (wid & 1) * 64;
    const int wn   = (wid >> 1) * 32;
    const int row0 = blockIdx.y * 128;
    const int col0 = blockIdx.x * 128;

    const int r_ld = tid >> 2;            // 0..63
    const int g_ld = (tid & 3) * 4;       // k-offset (floats)
    const uint32_t sm0 = smem_u32(sm);

    float acc[4][4][4];
#pragma unroll
    for (int i = 0; i < 4; i++)
#pragma unroll
        for (int j = 0; j < 4; j++)
#pragma unroll
            for (int q = 0; q < 4; q++) acc[i][j][q] = 0.0f;

    const int KT = K >> 4;   // K / 16

    auto issue = [&](int slot, int kt) {
        const uint32_t sa = sm0 + (slot * 2 * TILE_W) * 4;
        const uint32_t sb = sa + TILE_W * 4;
        const float* ga = A + (size_t)(row0 + r_ld) * lda + kt * 16 + g_ld;
        const float* gb = B + (size_t)(col0 + r_ld) * ldb + kt * 16 + g_ld;
        cp16(sa + (r_ld * SW + g_ld) * 4, ga);
        cp16(sa + ((r_ld + 64) * SW + g_ld) * 4, ga + (size_t)64 * lda);
        cp16(sb + (r_ld * SW + g_ld) * 4, gb);
        cp16(sb + ((r_ld + 64) * SW + g_ld) * 4, gb + (size_t)64 * ldb);
    };

    // prologue: 3 stages in flight
    issue(0, 0); cp_commit();
    issue(1, 1); cp_commit();
    issue(2, 2); cp_commit();

    for (int kt = 0; kt < KT; kt++) {
        asm volatile("cp.async.wait_group 2;" ::: "memory");
        __syncthreads();
        // slot (kt+3)&3 == (kt-1)&3: all warps finished kt-1 before the sync.
        if (kt + 3 < KT) issue((kt + 3) & 3, kt + 3);
        cp_commit();

        const float* Sa = sm + ((kt & 3) * 2) * TILE_W;
        const float* Sb = Sa + TILE_W;
        const float* pa = Sa + (wm + gid) * SW;   // per-warp row base
        const float* pb = Sb + (wn + gid) * SW;

#pragma unroll
        for (int ks = 0; ks < 2; ks++) {
            const int kw = ks * 8 + tig;
            uint32_t af[4][4], bf[4][2];
#pragma unroll
            for (int mt = 0; mt < 4; mt++) {
                af[mt][0] = __float_as_uint(pa[(mt * 16) * SW + kw]);
                af[mt][1] = __float_as_uint(pa[(mt * 16 + 8) * SW + kw]);
                af[mt][2] = __float_as_uint(pa[(mt * 16) * SW + kw + 4]);
                af[mt][3] = __float_as_uint(pa[(mt * 16 + 8) * SW + kw + 4]);
            }
#pragma unroll
            for (int nt = 0; nt < 4; nt++) {
                bf[nt][0] = __float_as_uint(pb[(nt * 8) * SW + kw]);
                bf[nt][1] = __float_as_uint(pb[(nt * 8) * SW + kw + 4]);
            }
#pragma unroll
            for (int mt = 0; mt < 4; mt++)
#pragma unroll
                for (int nt = 0; nt < 4; nt++)
                    mma_tf32(acc[mt][nt], af[mt], bf[nt]);
        }
    }

    // Epilogue: c0/c1 at (row, 2*tig), c2/c3 at (row+8, 2*tig)
#pragma unroll
    for (int mt = 0; mt < 4; mt++) {
        const int r = row0 + wm + mt * 16 + gid;
        float inv0 = 1.0f, inv1 = 1.0f;
        if (DIV) { inv0 = rowinv[r]; inv1 = rowinv[r + 8]; }
#pragma unroll
        for (int nt = 0; nt < 4; nt++) {
            const int c = col0 + wn + nt * 8 + 2 * tig;
            float o0 = acc[mt][nt][0] * scale, o1 = acc[mt][nt][1] * scale;
            float o2 = acc[mt][nt][2] * scale, o3 = acc[mt][nt][3] * scale;
            if (EPI == 2) {
                o0 = __expf(o0); o1 = __expf(o1);
                o2 = __expf(o2); o3 = __expf(o3);
            }
            if (EPI >= 1) {
                o0 = round_tf32f(o0); o1 = round_tf32f(o1);
                o2 = round_tf32f(o2); o3 = round_tf32f(o3);
            }
            if (DIV) { o0 *= inv0; o1 *= inv0; o2 *= inv1; o3 *= inv1; }
            *(float2*)(C + (size_t)r * ldc + c)       = make_float2(o0, o1);
            *(float2*)(C + (size_t)(r + 8) * ldc + c) = make_float2(o2, o3);
        }
    }
}

// ---------------------------------------------------------------------------
// Row-sum reciprocal: rinv[r] = 1 / sum(P[r, :]).  One block per row.
// ---------------------------------------------------------------------------
__global__ __launch_bounds__(256)
void row_inv(const float* __restrict__ P, float* __restrict__ rinv, int N)
{
    __shared__ float red[32];
    const int tid  = threadIdx.x;
    const int lane = tid & 31;
    const int warp = tid >> 5;
    const float4* row4 = (const float4*)(P + (size_t)blockIdx.x * N);

    float s = 0.0f;
    for (int i = tid; i < N / 4; i += 256) {
        float4 v = row4[i];
        s += (v.x + v.y) + (v.z + v.w);
    }
#pragma unroll
    for (int o = 16; o > 0; o >>= 1)
        s += __shfl_xor_sync(0xffffffffu, s, o);
    if (lane == 0) red[warp] = s;
    __syncthreads();
    if (tid < 32) {
        float v = (tid < 8) ? red[tid] : 0.0f;
#pragma unroll
        for (int o = 4; o > 0; o >>= 1)
            v += __shfl_xor_sync(0xffffffffu, v, o);
        if (tid == 0) rinv[blockIdx.x] = 1.0f / v;
    }
}

// ---------------------------------------------------------------------------
extern "C" void kernel_launch(void* const* d_in, const int* in_sizes, int n_in,
                              void* d_out, int out_size)
{
    const float* x  = (const float*)d_in[0];
    const float* Wq = (const float*)d_in[1];
    const float* Wk = (const float*)d_in[2];
    const float* Wv = (const float*)d_in[3];
    float* out = (float*)d_out;

    float *xp, *wqkp, *wvp, *qkp, *vp, *sp, *rip;
    cudaGetSymbolAddress((void**)&xp,   g_x);
    cudaGetSymbolAddress((void**)&wqkp, g_wqk);
    cudaGetSymbolAddress((void**)&wvp,  g_wv);
    cudaGetSymbolAddress((void**)&qkp,  g_qk);
    cudaGetSymbolAddress((void**)&vp,   g_v);
    cudaGetSymbolAddress((void**)&sp,   g_s);
    cudaGetSymbolAddress((void**)&rip,  g_rinv);

    cudaFuncSetAttribute(gemm_mma<1, false>, cudaFuncAttributeMaxDynamicSharedMemorySize, SMEM_BYTES);
    cudaFuncSetAttribute(gemm_mma<2, false>, cudaFuncAttributeMaxDynamicSharedMemorySize, SMEM_BYTES);
    cudaFuncSetAttribute(gemm_mma<0, true>,  cudaFuncAttributeMaxDynamicSharedMemorySize, SMEM_BYTES);

    const float scale = 1.0f / 32.0f;  // 1/sqrt(1024)

    // tf32 pre-rounding of raw inputs ([Wq;Wk] packed for the merged GEMM)
    round_arr<<<(SEQ * DIM / 4 + 255) / 256, 256>>>(x,  xp,   SEQ * DIM / 4);
    round_arr<<<(DIM * DIM / 4 + 255) / 256, 256>>>(Wq, wqkp, DIM * DIM / 4);
    round_arr<<<(DIM * DIM / 4 + 255) / 256, 256>>>(Wk, wqkp + DIM * DIM, DIM * DIM / 4);
    round_arr<<<(DIM * DIM / 4 + 255) / 256, 256>>>(Wv, wvp,  DIM * DIM / 4);

    // [Q|K] = X @ [Wq;Wk]^T   [4096, 2048]   (rounded, 512 CTAs)
    gemm_mma<1, false><<<dim3(2 * DIM / 128, SEQ / 128), 256, SMEM_BYTES>>>(
        xp, wqkp, qkp, DIM, DIM, DIM, 2 * DIM, 1.0f, nullptr);
    // V^T = Wv @ X^T   [1024, 4096]   (rounded)
    gemm_mma<1, false><<<dim3(SEQ / 128, DIM / 128), 256, SMEM_BYTES>>>(
        wvp, xp, vp, DIM, DIM, DIM, SEQ, 1.0f, nullptr);
    // P = exp((Q @ K^T) / 32)   [4096, 4096]   (unnormalized, rounded)
    gemm_mma<2, false><<<dim3(SEQ / 128, SEQ / 128), 256, SMEM_BYTES>>>(
        qkp, qkp + DIM, sp, DIM, 2 * DIM, 2 * DIM, SEQ, scale, nullptr);
    // rinv[r] = 1 / rowsum(P)
    row_inv<<<SEQ, 256>>>(sp, rip, SEQ);
    // O = (P @ V) * rinv   [4096, 1024]
    gemm_mma<0, true><<<dim3(DIM / 128, SEQ / 128), 256, SMEM_BYTES>>>(
        sp, vp, out, SEQ, SEQ, SEQ, DIM, 1.0f, rip);
}